// round 6
// baseline (speedup 1.0000x reference)
#include <cuda_runtime.h>

// LIF membrane update:
//   v_new[b,n] = ALPHA*v[b,n] + sum_i x[b,i,n]*w[i,n] - V_TH*z[b,n]
//   z_new[b,n] = (v_new[b,n] - V_TH > 0) ? 1 : 0
// Shapes: x[128,1024,512], w[1024,512], v[128,512], z[128,512]
//
// DRAM-page-locality version: each warp reads WHOLE 2KB x-rows sequentially
// (4 back-to-back 512B warp loads per row), so every DRAM page is opened
// once and streamed. Grid = 128 batches x 4 i-slices = 512 blocks (single
// wave). Cross-block i-reduction via L2 partials + atomic last-block epilogue.

#define B_     128
#define N_IN_  1024
#define NN_    512
#define NN4_   (NN_ / 4)              // 128 float4 per n-row (2KB)
#define ALPHA_ 0.995f
#define V_TH_  2.0f

#define WARPS    8
#define THREADS  (WARPS * 32)         // 256
#define ISLICES  4
#define IWARP    (N_IN_ / ISLICES / WARPS)   // 32 rows per warp

// partials: [b(128)][sl(4)][n4(128)] float4 = 1 MB (L2-resident)
__device__ float4 g_partial[B_ * ISLICES * NN4_];
__device__ int    g_cnt[B_];          // zero-init; reset by last block

__global__ __launch_bounds__(THREADS, 4)
void lif_kernel(const float4* __restrict__ x,
                const float4* __restrict__ w,
                const float4* __restrict__ v,
                const float4* __restrict__ z,
                float4* __restrict__ out)
{
    __shared__ float4 red[WARPS][4][32];   // 16 KB
    __shared__ int s_last;

    const int bx   = blockIdx.x;
    const int sl   = bx & 3;               // i-slice
    const int b    = bx >> 2;              // batch
    const int lane = threadIdx.x & 31;
    const int wid  = threadIdx.x >> 5;

    const int i0 = sl * (N_IN_ / ISLICES) + wid * IWARP;

    const float4* xb = x + ((size_t)b * N_IN_ + i0) * NN4_;
    const float4* wb = w + (size_t)i0 * NN4_;

    float4 a0 = make_float4(0.f,0.f,0.f,0.f);
    float4 a1 = a0, a2 = a0, a3 = a0;

    // 32 rows, each row = 2KB read as 4 contiguous 512B warp loads
    #pragma unroll 2
    for (int r = 0; r < IWARP; ++r) {
        const float4* xr = xb + (size_t)r * NN4_;
        const float4* wr = wb + (size_t)r * NN4_;

        float4 x0 = __ldcs(xr      + lane);
        float4 x1 = __ldcs(xr + 32 + lane);
        float4 x2 = __ldcs(xr + 64 + lane);
        float4 x3 = __ldcs(xr + 96 + lane);
        float4 w0 = __ldg (wr      + lane);
        float4 w1 = __ldg (wr + 32 + lane);
        float4 w2 = __ldg (wr + 64 + lane);
        float4 w3 = __ldg (wr + 96 + lane);

        a0.x += x0.x * w0.x; a0.y += x0.y * w0.y;
        a0.z += x0.z * w0.z; a0.w += x0.w * w0.w;
        a1.x += x1.x * w1.x; a1.y += x1.y * w1.y;
        a1.z += x1.z * w1.z; a1.w += x1.w * w1.w;
        a2.x += x2.x * w2.x; a2.y += x2.y * w2.y;
        a2.z += x2.z * w2.z; a2.w += x2.w * w2.w;
        a3.x += x3.x * w3.x; a3.y += x3.y * w3.y;
        a3.z += x3.z * w3.z; a3.w += x3.w * w3.w;
    }

    red[wid][0][lane] = a0;
    red[wid][1][lane] = a1;
    red[wid][2][lane] = a2;
    red[wid][3][lane] = a3;
    __syncthreads();

    // intra-block reduce over 8 warps -> this slice's partial [128 float4]
    if (threadIdx.x < 4 * 32) {
        const int q = threadIdx.x >> 5;
        float4 s = red[0][q][lane];
        #pragma unroll
        for (int k = 1; k < WARPS; ++k) {
            float4 t = red[k][q][lane];
            s.x += t.x; s.y += t.y; s.z += t.z; s.w += t.w;
        }
        g_partial[((size_t)b * ISLICES + sl) * NN4_ + q * 32 + lane] = s;
    }

    // last-arriving slice block for this batch finishes reduction + epilogue
    __threadfence();
    if (threadIdx.x == 0)
        s_last = (atomicAdd(&g_cnt[b], 1) == ISLICES - 1);
    __syncthreads();

    if (s_last) {
        if (threadIdx.x < NN4_) {
            const int n4 = threadIdx.x;
            float4 sum = make_float4(0.f,0.f,0.f,0.f);
            #pragma unroll
            for (int s2 = 0; s2 < ISLICES; ++s2) {
                float4 p = g_partial[((size_t)b * ISLICES + s2) * NN4_ + n4];
                sum.x += p.x; sum.y += p.y; sum.z += p.z; sum.w += p.w;
            }

            const int on = b * NN4_ + n4;
            float4 vv = v[on];
            float4 zz = z[on];

            float4 vn;
            vn.x = ALPHA_ * vv.x + sum.x - V_TH_ * zz.x;
            vn.y = ALPHA_ * vv.y + sum.y - V_TH_ * zz.y;
            vn.z = ALPHA_ * vv.z + sum.z - V_TH_ * zz.z;
            vn.w = ALPHA_ * vv.w + sum.w - V_TH_ * zz.w;

            float4 zn;
            zn.x = (vn.x - V_TH_ > 0.f) ? 1.f : 0.f;
            zn.y = (vn.y - V_TH_ > 0.f) ? 1.f : 0.f;
            zn.z = (vn.z - V_TH_ > 0.f) ? 1.f : 0.f;
            zn.w = (vn.w - V_TH_ > 0.f) ? 1.f : 0.f;

            out[on] = vn;                 // v_new: first B*NN floats
            out[B_ * NN4_ + on] = zn;     // z_new: next B*NN floats
        }
        if (threadIdx.x == 0)
            g_cnt[b] = 0;                 // reset for next graph replay
    }
}

extern "C" void kernel_launch(void* const* d_in, const int* in_sizes, int n_in,
                              void* d_out, int out_size)
{
    const float4* x = (const float4*)d_in[0];  // [128,1024,512] f32
    const float4* w = (const float4*)d_in[1];  // [1024,512]     f32
    const float4* v = (const float4*)d_in[2];  // [128,512]      f32
    const float4* z = (const float4*)d_in[3];  // [128,512]      f32
    float4* out = (float4*)d_out;              // [2,128,512]    f32

    (void)in_sizes; (void)n_in; (void)out_size;

    lif_kernel<<<B_ * ISLICES, THREADS>>>(x, w, v, z, out);
}

// round 7
// speedup vs baseline: 1.0023x; 1.0023x over previous
#include <cuda_runtime.h>
#include <cstdint>

// LIF membrane update:
//   v_new[b,n] = ALPHA*v[b,n] + sum_i x[b,i,n]*w[i,n] - V_TH*z[b,n]
//   z_new[b,n] = (v_new[b,n] - V_TH > 0) ? 1 : 0
// Shapes: x[128,1024,512], w[1024,512], v[128,512], z[128,512]
//
// R4 grid (512 blocks = 128 b x 4 ntiles, 256 thr, 4 CTAs/SM, single wave),
// but x is streamed through a 4-deep cp.async smem pipeline so in-flight
// DRAM bytes are bounded by smem (96KB/SM) instead of the register file.

#define B_     128
#define N_IN_  1024
#define NN_    512
#define NN4_   (NN_ / 4)          // 128 float4 per n-row
#define ALPHA_ 0.995f
#define V_TH_  2.0f

#define WARPS      8
#define THREADS    (WARPS * 32)   // 256
#define STAGE_ROWS 16
#define DEPTH      4
#define NSTAGES    (N_IN_ / STAGE_ROWS)   // 64

__device__ __forceinline__ void cp_async16(void* smem_dst, const void* gmem_src) {
    uint32_t s = (uint32_t)__cvta_generic_to_shared(smem_dst);
    asm volatile("cp.async.cg.shared.global [%0], [%1], 16;\n"
                 :: "r"(s), "l"(gmem_src));
}
__device__ __forceinline__ void cp_commit() {
    asm volatile("cp.async.commit_group;\n");
}
template <int N>
__device__ __forceinline__ void cp_wait() {
    asm volatile("cp.async.wait_group %0;\n" :: "n"(N));
}

__global__ __launch_bounds__(THREADS, 4)
void lif_kernel(const float4* __restrict__ x,
                const float4* __restrict__ w,
                const float4* __restrict__ v,
                const float4* __restrict__ z,
                float4* __restrict__ out)
{
    __shared__ float4 xbuf[DEPTH][STAGE_ROWS][32];   // 32 KB
    __shared__ float4 red[WARPS][32];                // 4 KB

    const int b    = blockIdx.x >> 2;
    const int nt   = blockIdx.x & 3;
    const int lane = threadIdx.x & 31;
    const int wid  = threadIdx.x >> 5;
    const int n4   = nt * 32 + lane;

    // per-thread cp.async source slots: chunk c = threadIdx.x and +256
    const int c0r = threadIdx.x >> 5, c0l = threadIdx.x & 31;       // row 0..7
    const int c1r = c0r + 8,          c1l = c0l;                    // row 8..15
    const float4* xbase = x + (size_t)b * N_IN_ * NN4_ + nt * 32;

    // prologue: prefetch stages 0..2
    #pragma unroll
    for (int s = 0; s < DEPTH - 1; ++s) {
        cp_async16(&xbuf[s][c0r][c0l], xbase + (size_t)(s * STAGE_ROWS + c0r) * NN4_ + c0l);
        cp_async16(&xbuf[s][c1r][c1l], xbase + (size_t)(s * STAGE_ROWS + c1r) * NN4_ + c1l);
        cp_commit();
    }

    float4 acc = make_float4(0.f, 0.f, 0.f, 0.f);
    const float4* wb = w + n4;
    const int r0base = 2 * wid;   // this warp's first row within a stage

    #pragma unroll 4
    for (int s = 0; s < NSTAGES; ++s) {
        cp_wait<DEPTH - 2>();      // stage s resident
        __syncthreads();           // all warps see stage s; buffer (s-1)%4 free

        if (s < NSTAGES - (DEPTH - 1)) {
            const int sp = s + DEPTH - 1;
            cp_async16(&xbuf[sp & 3][c0r][c0l], xbase + (size_t)(sp * STAGE_ROWS + c0r) * NN4_ + c0l);
            cp_async16(&xbuf[sp & 3][c1r][c1l], xbase + (size_t)(sp * STAGE_ROWS + c1r) * NN4_ + c1l);
            cp_commit();
        } else {
            cp_commit();           // keep group count in lockstep for cp_wait
        }

        // compute stage s: warp wid handles rows 2*wid, 2*wid+1
        const int gr = s * STAGE_ROWS + r0base;
        float4 xa = xbuf[s & 3][r0base][lane];
        float4 xc = xbuf[s & 3][r0base + 1][lane];
        float4 wa = __ldg(&wb[(size_t)gr * NN4_]);
        float4 wc = __ldg(&wb[(size_t)(gr + 1) * NN4_]);

        acc.x += xa.x * wa.x; acc.y += xa.y * wa.y;
        acc.z += xa.z * wa.z; acc.w += xa.w * wa.w;
        acc.x += xc.x * wc.x; acc.y += xc.y * wc.y;
        acc.z += xc.z * wc.z; acc.w += xc.w * wc.w;
    }

    red[wid][lane] = acc;
    __syncthreads();

    if (threadIdx.x < 32) {
        float4 sum = red[0][lane];
        #pragma unroll
        for (int k = 1; k < WARPS; ++k) {
            float4 t = red[k][lane];
            sum.x += t.x; sum.y += t.y; sum.z += t.z; sum.w += t.w;
        }

        const int on = b * NN4_ + n4;
        float4 vv = v[on];
        float4 zz = z[on];

        float4 vn;
        vn.x = ALPHA_ * vv.x + sum.x - V_TH_ * zz.x;
        vn.y = ALPHA_ * vv.y + sum.y - V_TH_ * zz.y;
        vn.z = ALPHA_ * vv.z + sum.z - V_TH_ * zz.z;
        vn.w = ALPHA_ * vv.w + sum.w - V_TH_ * zz.w;

        float4 zn;
        zn.x = (vn.x - V_TH_ > 0.f) ? 1.f : 0.f;
        zn.y = (vn.y - V_TH_ > 0.f) ? 1.f : 0.f;
        zn.z = (vn.z - V_TH_ > 0.f) ? 1.f : 0.f;
        zn.w = (vn.w - V_TH_ > 0.f) ? 1.f : 0.f;

        out[on] = vn;                  // v_new: first B*NN floats
        out[B_ * NN4_ + on] = zn;      // z_new: next B*NN floats
    }
}

extern "C" void kernel_launch(void* const* d_in, const int* in_sizes, int n_in,
                              void* d_out, int out_size)
{
    const float4* x = (const float4*)d_in[0];  // [128,1024,512] f32
    const float4* w = (const float4*)d_in[1];  // [1024,512]     f32
    const float4* v = (const float4*)d_in[2];  // [128,512]      f32
    const float4* z = (const float4*)d_in[3];  // [128,512]      f32
    float4* out = (float4*)d_out;              // [2,128,512]    f32

    (void)in_sizes; (void)n_in; (void)out_size;

    lif_kernel<<<B_ * 4, THREADS>>>(x, w, v, z, out);
}

// round 8
// speedup vs baseline: 1.1250x; 1.1224x over previous
#include <cuda_runtime.h>

// LIF membrane update:
//   v_new[b,n] = ALPHA*v[b,n] + sum_i x[b,i,n]*w[i,n] - V_TH*z[b,n]
//   z_new[b,n] = (v_new[b,n] - V_TH > 0) ? 1 : 0
// Shapes: x[128,1024,512], w[1024,512], v[128,512], z[128,512]
//
// R4's winning access pattern (per warp: 4-batched 512B loads at 2KB stride),
// but the i-range is split across 2 blocks -> 1024 blocks on 592 CTA slots.
// Backfill smooths per-SM finish-time spread; tail quantum is half a CTA.
// Cross-block combine is warp0-only: partial + fence + atomic counter; the
// last-arriving sibling adds the other partial and runs the LIF epilogue.

#define B_     128
#define N_IN_  1024
#define NN_    512
#define NN4_   (NN_ / 4)          // 128 float4 per n-row
#define ALPHA_ 0.995f
#define V_TH_  2.0f

#define WARPS   8
#define THREADS (WARPS * 32)      // 256
#define IPER    64                // i-rows per warp (half of R4)

// partials: [group(512)][isl(2)][lane(32)] float4 = 512 KB (L2-resident)
__device__ float4 g_partial[512 * 2 * 32];
__device__ int    g_cnt[512];     // zero-init; reset by the finishing block

__global__ __launch_bounds__(THREADS, 4)
void lif_kernel(const float4* __restrict__ x,
                const float4* __restrict__ w,
                const float4* __restrict__ v,
                const float4* __restrict__ z,
                float4* __restrict__ out)
{
    __shared__ float4 red[WARPS][32];   // 4 KB

    const int group = blockIdx.x & 511;      // (b, nt)
    const int isl   = blockIdx.x >> 9;       // i-half: 0 or 1
    const int b     = group >> 2;
    const int nt    = group & 3;
    const int lane  = threadIdx.x & 31;
    const int wid   = threadIdx.x >> 5;
    const int n4    = nt * 32 + lane;

    const int i0 = isl * (N_IN_ / 2) + wid * IPER;
    const float4* xb = x + ((size_t)b * N_IN_ + i0) * NN4_ + n4;
    const float4* wb = w + (size_t)i0 * NN4_ + n4;

    float4 acc = make_float4(0.f, 0.f, 0.f, 0.f);

    for (int i = 0; i < IPER; i += 4) {
        // 4 independent DRAM loads (2KB apart) + 4 L2 loads, batched
        float4 x0 = __ldcs(&xb[(size_t)(i + 0) * NN4_]);
        float4 x1 = __ldcs(&xb[(size_t)(i + 1) * NN4_]);
        float4 x2 = __ldcs(&xb[(size_t)(i + 2) * NN4_]);
        float4 x3 = __ldcs(&xb[(size_t)(i + 3) * NN4_]);
        float4 w0 = __ldg (&wb[(size_t)(i + 0) * NN4_]);
        float4 w1 = __ldg (&wb[(size_t)(i + 1) * NN4_]);
        float4 w2 = __ldg (&wb[(size_t)(i + 2) * NN4_]);
        float4 w3 = __ldg (&wb[(size_t)(i + 3) * NN4_]);

        acc.x += x0.x * w0.x; acc.y += x0.y * w0.y;
        acc.z += x0.z * w0.z; acc.w += x0.w * w0.w;
        acc.x += x1.x * w1.x; acc.y += x1.y * w1.y;
        acc.z += x1.z * w1.z; acc.w += x1.w * w1.w;
        acc.x += x2.x * w2.x; acc.y += x2.y * w2.y;
        acc.z += x2.z * w2.z; acc.w += x2.w * w2.w;
        acc.x += x3.x * w3.x; acc.y += x3.y * w3.y;
        acc.z += x3.z * w3.z; acc.w += x3.w * w3.w;
    }

    red[wid][lane] = acc;
    __syncthreads();

    // warp0 finishes everything; other warps are done
    if (wid == 0) {
        float4 sum = red[0][lane];
        #pragma unroll
        for (int k = 1; k < WARPS; ++k) {
            float4 t = red[k][lane];
            sum.x += t.x; sum.y += t.y; sum.z += t.z; sum.w += t.w;
        }

        // publish this half's partial
        g_partial[((size_t)group * 2 + isl) * 32 + lane] = sum;
        __threadfence();          // order partial store before counter bump
        __syncwarp();

        int last = 0;
        if (lane == 0)
            last = (atomicAdd(&g_cnt[group], 1) == 1);
        last = __shfl_sync(0xFFFFFFFFu, last, 0);

        if (last) {
            __threadfence();      // acquire side: sibling partial visible
            float4 p = __ldcg(&g_partial[((size_t)group * 2 + (isl ^ 1)) * 32 + lane]);
            sum.x += p.x; sum.y += p.y; sum.z += p.z; sum.w += p.w;

            const int on = b * NN4_ + n4;
            float4 vv = v[on];
            float4 zz = z[on];

            float4 vn;
            vn.x = ALPHA_ * vv.x + sum.x - V_TH_ * zz.x;
            vn.y = ALPHA_ * vv.y + sum.y - V_TH_ * zz.y;
            vn.z = ALPHA_ * vv.z + sum.z - V_TH_ * zz.z;
            vn.w = ALPHA_ * vv.w + sum.w - V_TH_ * zz.w;

            float4 zn;
            zn.x = (vn.x - V_TH_ > 0.f) ? 1.f : 0.f;
            zn.y = (vn.y - V_TH_ > 0.f) ? 1.f : 0.f;
            zn.z = (vn.z - V_TH_ > 0.f) ? 1.f : 0.f;
            zn.w = (vn.w - V_TH_ > 0.f) ? 1.f : 0.f;

            out[on] = vn;                 // v_new: first B*NN floats
            out[B_ * NN4_ + on] = zn;     // z_new: next B*NN floats

            if (lane == 0)
                g_cnt[group] = 0;         // reset for next graph replay
        }
    }
}

extern "C" void kernel_launch(void* const* d_in, const int* in_sizes, int n_in,
                              void* d_out, int out_size)
{
    const float4* x = (const float4*)d_in[0];  // [128,1024,512] f32
    const float4* w = (const float4*)d_in[1];  // [1024,512]     f32
    const float4* v = (const float4*)d_in[2];  // [128,512]      f32
    const float4* z = (const float4*)d_in[3];  // [128,512]      f32
    float4* out = (float4*)d_out;              // [2,128,512]    f32

    (void)in_sizes; (void)n_in; (void)out_size;

    lif_kernel<<<512 * 2, THREADS>>>(x, w, v, z, out);
}

// round 9
// speedup vs baseline: 1.1731x; 1.0428x over previous
#include <cuda_runtime.h>

// LIF membrane update:
//   v_new[b,n] = ALPHA*v[b,n] + sum_i x[b,i,n]*w[i,n] - V_TH*z[b,n]
//   z_new[b,n] = (v_new[b,n] - V_TH > 0) ? 1 : 0
// Shapes: x[128,1024,512], w[1024,512], v[128,512], z[128,512]
//
// Clean LTS-cap test: each block handles 2 batches, so every w load (L2 hit)
// feeds 2 x loads -> w L2 traffic halves vs R4. No cross-block reduction, no
// atomics. Grid = 64 bgroups x 4 ntiles = 256 blocks x 512 threads (16 warps,
// warp = 64 i-rows x 2 batches), 2 CTAs/SM, single wave.

#define B_     128
#define N_IN_  1024
#define NN_    512
#define NN4_   (NN_ / 4)          // 128 float4 per n-row
#define ALPHA_ 0.995f
#define V_TH_  2.0f

#define WARPS   16
#define THREADS (WARPS * 32)      // 512
#define IPER    (N_IN_ / WARPS)   // 64 i-rows per warp
#define XSTR    ((size_t)N_IN_ * NN4_)   // per-batch float4 stride

__global__ __launch_bounds__(THREADS, 2)
void lif_kernel(const float4* __restrict__ x,
                const float4* __restrict__ w,
                const float4* __restrict__ v,
                const float4* __restrict__ z,
                float4* __restrict__ out)
{
    __shared__ float4 red[WARPS][2][32];   // 16 KB

    const int bg   = blockIdx.x >> 2;      // batch pair
    const int nt   = blockIdx.x & 3;       // n-tile
    const int lane = threadIdx.x & 31;
    const int wid  = threadIdx.x >> 5;
    const int n4   = nt * 32 + lane;

    const int b0 = bg * 2;
    const int i0 = wid * IPER;

    const float4* xb = x + ((size_t)b0 * N_IN_ + i0) * NN4_ + n4;
    const float4* wb = w + (size_t)i0 * NN4_ + n4;

    float4 a0 = make_float4(0.f, 0.f, 0.f, 0.f);
    float4 a1 = a0;

    for (int i = 0; i < IPER; i += 2) {
        const size_t r0 = (size_t)i * NN4_;
        const size_t r1 = (size_t)(i + 1) * NN4_;
        // 4 x loads (2 rows x 2 batches) + 2 w loads; w reused across batches
        float4 xa0 = __ldcs(&xb[r0]);
        float4 xa1 = __ldcs(&xb[r1]);
        float4 xb0 = __ldcs(&xb[r0 + XSTR]);
        float4 xb1 = __ldcs(&xb[r1 + XSTR]);
        float4 w0  = __ldg (&wb[r0]);
        float4 w1  = __ldg (&wb[r1]);

        a0.x += xa0.x * w0.x; a0.y += xa0.y * w0.y;
        a0.z += xa0.z * w0.z; a0.w += xa0.w * w0.w;
        a0.x += xa1.x * w1.x; a0.y += xa1.y * w1.y;
        a0.z += xa1.z * w1.z; a0.w += xa1.w * w1.w;

        a1.x += xb0.x * w0.x; a1.y += xb0.y * w0.y;
        a1.z += xb0.z * w0.z; a1.w += xb0.w * w0.w;
        a1.x += xb1.x * w1.x; a1.y += xb1.y * w1.y;
        a1.z += xb1.z * w1.z; a1.w += xb1.w * w1.w;
    }

    red[wid][0][lane] = a0;
    red[wid][1][lane] = a1;
    __syncthreads();

    if (threadIdx.x < 2 * 32) {
        const int q = threadIdx.x >> 5;   // batch within pair
        float4 sum = red[0][q][lane];
        #pragma unroll
        for (int k = 1; k < WARPS; ++k) {
            float4 t = red[k][q][lane];
            sum.x += t.x; sum.y += t.y; sum.z += t.z; sum.w += t.w;
        }

        const int b  = b0 + q;
        const int on = b * NN4_ + n4;
        float4 vv = v[on];
        float4 zz = z[on];

        float4 vn;
        vn.x = ALPHA_ * vv.x + sum.x - V_TH_ * zz.x;
        vn.y = ALPHA_ * vv.y + sum.y - V_TH_ * zz.y;
        vn.z = ALPHA_ * vv.z + sum.z - V_TH_ * zz.z;
        vn.w = ALPHA_ * vv.w + sum.w - V_TH_ * zz.w;

        float4 zn;
        zn.x = (vn.x - V_TH_ > 0.f) ? 1.f : 0.f;
        zn.y = (vn.y - V_TH_ > 0.f) ? 1.f : 0.f;
        zn.z = (vn.z - V_TH_ > 0.f) ? 1.f : 0.f;
        zn.w = (vn.w - V_TH_ > 0.f) ? 1.f : 0.f;

        out[on] = vn;                  // v_new: first B*NN floats
        out[B_ * NN4_ + on] = zn;      // z_new: next B*NN floats
    }
}

extern "C" void kernel_launch(void* const* d_in, const int* in_sizes, int n_in,
                              void* d_out, int out_size)
{
    const float4* x = (const float4*)d_in[0];  // [128,1024,512] f32
    const float4* w = (const float4*)d_in[1];  // [1024,512]     f32
    const float4* v = (const float4*)d_in[2];  // [128,512]      f32
    const float4* z = (const float4*)d_in[3];  // [128,512]      f32
    float4* out = (float4*)d_out;              // [2,128,512]    f32

    (void)in_sizes; (void)n_in; (void)out_size;

    lif_kernel<<<(B_ / 2) * 4, THREADS>>>(x, w, v, z, out);
}